// round 1
// baseline (speedup 1.0000x reference)
#include <cuda_runtime.h>
#include <cuda_bf16.h>
#include <math.h>

#define BB   8
#define N1   2048
#define N2   512
#define DD   128
#define KK   32
#define R3   27
#define NCH  81      // 3*27
#define FC   192

// ---------------- scratch (device globals; no allocs allowed) ----------------
__device__ float  g_corr[BB * N1 * N2];          // 32 MB
__device__ float  g_vol [BB * NCH * N1];         // 5.3 MB
__device__ float  g_h1  [BB * 128 * N1];         // 8.4 MB
__device__ int    g_nbr [BB * N1 * KK];          // 2 MB
__device__ double g_volsum[BB][8][2];            // sum, sumsq per (b, group)
__device__ double g_knnmom[BB][14];              // mu(4) + upper-tri E[ee^T](10)
__device__ float  g_volstat[BB][8][2];           // mean, rstd
__device__ float  g_knnstat[BB][8][2];           // mean, rstd

// ---------------- K0: zero the stat accumulators ----------------
__global__ void zero_stats_kernel() {
    int t = threadIdx.x;
    double* vs = &g_volsum[0][0][0];
    double* km = &g_knnmom[0][0];
    if (t < BB * 8 * 2) vs[t] = 0.0;
    if (t < BB * 14)    km[t] = 0.0;
}

// ---------------- K1: corr = fmap1^T @ fmap2 / sqrt(D) ----------------
// tile 64x64, 256 threads, 4x4 per thread
__global__ void corr_kernel(const float* __restrict__ f1, const float* __restrict__ f2) {
    int b  = blockIdx.z;
    int n0 = blockIdx.x * 64;
    int m0 = blockIdx.y * 64;
    __shared__ float As[16][64];
    __shared__ float Bs[16][64];
    int tx = threadIdx.x & 15;
    int ty = threadIdx.x >> 4;
    float acc[4][4];
#pragma unroll
    for (int i = 0; i < 4; i++)
#pragma unroll
        for (int j = 0; j < 4; j++) acc[i][j] = 0.f;

    const float* A = f1 + (size_t)b * DD * N1;
    const float* Bp = f2 + (size_t)b * DD * N2;
    for (int k0 = 0; k0 < DD; k0 += 16) {
#pragma unroll
        for (int i = threadIdx.x; i < 16 * 64; i += 256) {
            int d = i >> 6, c = i & 63;
            As[d][c] = A[(k0 + d) * N1 + n0 + c];
            Bs[d][c] = Bp[(k0 + d) * N2 + m0 + c];
        }
        __syncthreads();
#pragma unroll
        for (int kk = 0; kk < 16; kk++) {
            float4 a = *(const float4*)&As[kk][ty * 4];
            float4 bb = *(const float4*)&Bs[kk][tx * 4];
            float av[4] = {a.x, a.y, a.z, a.w};
            float bv[4] = {bb.x, bb.y, bb.z, bb.w};
#pragma unroll
            for (int i = 0; i < 4; i++)
#pragma unroll
                for (int j = 0; j < 4; j++) acc[i][j] += av[i] * bv[j];
        }
        __syncthreads();
    }
    const float s = 0.08838834764831845f;  // 1/sqrt(128)
#pragma unroll
    for (int i = 0; i < 4; i++) {
        int n = n0 + ty * 4 + i;
        float* dst = g_corr + ((size_t)b * N1 + n) * N2 + m0 + tx * 4;
#pragma unroll
        for (int j = 0; j < 4; j++) dst[j] = acc[i][j] * s;
    }
}

// ---------------- K2: per-row pass: voxel bins + KNN select + e-moments ----------------
// one warp per row n; 8 rows per block; grid (N1/8, B)
__global__ void row_kernel(const float* __restrict__ coords,
                           const float* __restrict__ coords2) {
    int b    = blockIdx.y;
    int warp = threadIdx.x >> 5;
    int lane = threadIdx.x & 31;
    int n    = blockIdx.x * 8 + warp;

    __shared__ float sadd[8][NCH];
    __shared__ float scnt[8][NCH];
    __shared__ int   sknn[8][KK];
    __shared__ float smom[14];

    if (threadIdx.x < 14) smom[threadIdx.x] = 0.f;
    for (int q = lane; q < NCH; q += 32) { sadd[warp][q] = 0.f; scnt[warp][q] = 0.f; }
    __syncthreads();

    float cx = coords[((size_t)b * N1 + n) * 3 + 0];
    float cy = coords[((size_t)b * N1 + n) * 3 + 1];
    float cz = coords[((size_t)b * N1 + n) * 3 + 2];
    const float* crow = g_corr + ((size_t)b * N1 + n) * N2;
    const float* c2 = coords2 + (size_t)b * N2 * 3;

    float dloc[16];
#pragma unroll 4
    for (int s = 0; s < 16; s++) {
        int m = lane + s * 32;
        float qx = c2[m * 3 + 0] - cx;
        float qy = c2[m * 3 + 1] - cy;
        float qz = c2[m * 3 + 2] - cz;
        dloc[s] = qx * qx + qy * qy + qz * qz;
        float mx = fmaxf(fabsf(qx), fmaxf(fabsf(qy), fabsf(qz)));
        if (mx < 1.5f) {
            float cv = crow[m];
#pragma unroll
            for (int lvl = 0; lvl < 3; lvl++) {
                float inv = (lvl == 0) ? 4.f : (lvl == 1 ? 2.f : 1.f);
                float vx = rintf(qx * inv), vy = rintf(qy * inv), vz = rintf(qz * inv);
                if (fabsf(vx) <= 1.f && fabsf(vy) <= 1.f && fabsf(vz) <= 1.f) {
                    int idx = lvl * 27 + ((int)vx + 1) * 9 + ((int)vy + 1) * 3 + ((int)vz + 1);
                    atomicAdd(&sadd[warp][idx], cv);
                    atomicAdd(&scnt[warp][idx], 1.f);
                }
            }
        }
    }
    __syncwarp();

    // top-32 smallest dist (index tiebreak = reference top_k semantics)
    for (int k = 0; k < KK; k++) {
        float bv = 3.4e38f; int bs = 16;
#pragma unroll
        for (int s = 0; s < 16; s++) {
            if (dloc[s] < bv) { bv = dloc[s]; bs = s; }
        }
        int bm = lane + bs * 32;
#pragma unroll
        for (int off = 16; off; off >>= 1) {
            float ov = __shfl_xor_sync(0xffffffffu, bv, off);
            int   om = __shfl_xor_sync(0xffffffffu, bm, off);
            if (ov < bv || (ov == bv && om < bm)) { bv = ov; bm = om; }
        }
        if (lane == (bm & 31)) {
            int ws = bm >> 5;
#pragma unroll
            for (int s = 0; s < 16; s++) if (s == ws) dloc[s] = 3.4e38f;
        }
        if (lane == 0) sknn[warp][k] = bm;
    }
    __syncwarp();

    int j = sknn[warp][lane];
    g_nbr[((size_t)b * N1 + n) * KK + lane] = j;
    float e0 = crow[j];
    float e1 = c2[j * 3 + 0] - cx;
    float e2 = c2[j * 3 + 1] - cy;
    float e3 = c2[j * 3 + 2] - cz;

    float mv[14] = { e0, e1, e2, e3,
                     e0*e0, e0*e1, e0*e2, e0*e3,
                     e1*e1, e1*e2, e1*e3,
                     e2*e2, e2*e3, e3*e3 };
#pragma unroll
    for (int i = 0; i < 14; i++) {
        float v = mv[i];
#pragma unroll
        for (int off = 16; off; off >>= 1) v += __shfl_xor_sync(0xffffffffu, v, off);
        if (lane == 0) atomicAdd(&smom[i], v);
    }

    // write voxel features (scatter mean)
    for (int q = lane; q < NCH; q += 32) {
        float cnt = scnt[warp][q];
        g_vol[((size_t)b * NCH + q) * N1 + n] = sadd[warp][q] / fmaxf(cnt, 1.f);
    }
    __syncthreads();
    if (threadIdx.x < 14) atomicAdd(&g_knnmom[b][threadIdx.x], (double)smom[threadIdx.x]);
}

// ---------------- K3: h1 = W1 @ vol + b1, plus GN partial stats ----------------
// grid (N1/128, B), 128 threads; each thread = one point
__global__ void h1_kernel(const float* __restrict__ W1, const float* __restrict__ b1) {
    int b = blockIdx.y;
    int n0 = blockIdx.x * 128;
    int t = threadIdx.x;
    __shared__ float sv[NCH][128];
    __shared__ float gs[8], gss[8];
    for (int i = t; i < NCH * 128; i += 128) {
        int q = i >> 7, c = i & 127;
        sv[q][c] = g_vol[((size_t)b * NCH + q) * N1 + n0 + c];
    }
    if (t < 8) { gs[t] = 0.f; gss[t] = 0.f; }
    __syncthreads();

    for (int g = 0; g < 8; g++) {
        float ls = 0.f, lss = 0.f;
        for (int c = g * 16; c < g * 16 + 16; c++) {
            float acc = b1[c];
            const float* w = W1 + c * NCH;
#pragma unroll 27
            for (int q = 0; q < NCH; q++) acc += w[q] * sv[q][t];
            g_h1[((size_t)b * 128 + c) * N1 + n0 + t] = acc;
            ls += acc; lss += acc * acc;
        }
        atomicAdd(&gs[g], ls);
        atomicAdd(&gss[g], lss);
    }
    __syncthreads();
    if (t < 8) {
        atomicAdd(&g_volsum[b][t][0], (double)gs[t]);
        atomicAdd(&g_volsum[b][t][1], (double)gss[t]);
    }
}

// ---------------- K4: finalize stats (vol GN + analytic knn GN) ----------------
__global__ void finalize_kernel(const float* __restrict__ Wk, const float* __restrict__ bk) {
    int t = threadIdx.x;
    if (t >= 64) return;
    int b = t >> 3, g = t & 7;

    // vol branch
    {
        double cnt = 16.0 * (double)N1;
        double mean = g_volsum[b][g][0] / cnt;
        double var = g_volsum[b][g][1] / cnt - mean * mean;
        g_volstat[b][g][0] = (float)mean;
        g_volstat[b][g][1] = (float)(1.0 / sqrt(var + 1e-5));
    }
    // knn branch (h = Wk e + bk is linear in e)
    {
        double cnt = (double)N1 * (double)KK;
        double mu[4];
#pragma unroll
        for (int i = 0; i < 4; i++) mu[i] = g_knnmom[b][i] / cnt;
        double S[4][4];
        const int pi[10][2] = {{0,0},{0,1},{0,2},{0,3},{1,1},{1,2},{1,3},{2,2},{2,3},{3,3}};
#pragma unroll
        for (int p = 0; p < 10; p++) {
            double v = g_knnmom[b][4 + p] / cnt;
            S[pi[p][0]][pi[p][1]] = v;
            S[pi[p][1]][pi[p][0]] = v;
        }
        double sm = 0.0, s2 = 0.0;
        for (int c = g * 8; c < g * 8 + 8; c++) {
            double w[4] = { (double)Wk[c*4+0], (double)Wk[c*4+1], (double)Wk[c*4+2], (double)Wk[c*4+3] };
            double bb = (double)bk[c];
            double wm = w[0]*mu[0] + w[1]*mu[1] + w[2]*mu[2] + w[3]*mu[3];
            double q = 0.0;
#pragma unroll
            for (int i = 0; i < 4; i++)
#pragma unroll
                for (int jj = 0; jj < 4; jj++) q += w[i] * S[i][jj] * w[jj];
            double m1 = wm + bb;
            double m2 = q + 2.0 * bb * wm + bb * bb;
            sm += m1; s2 += m2;
        }
        sm *= 0.125; s2 *= 0.125;
        double var = s2 - sm * sm;
        g_knnstat[b][g][0] = (float)sm;
        g_knnstat[b][g][1] = (float)(1.0 / sqrt(var + 1e-5));
    }
}

// ---------------- K5: vol_out = W2 @ prelu(GN(h1)) + b2 -> out ----------------
// grid (N1/32, B), 256 threads
__global__ void volout_kernel(const float* __restrict__ g1, const float* __restrict__ be1,
                              const float* __restrict__ a1p,
                              const float* __restrict__ W2, const float* __restrict__ b2,
                              float* __restrict__ out) {
    int b = blockIdx.y;
    int n0 = blockIdx.x * 32;
    int t = threadIdx.x;
    __shared__ float hn[128][33];
    float a1 = a1p[0];
    for (int i = t; i < 128 * 32; i += 256) {
        int c = i >> 5, nn = i & 31;
        int g = c >> 4;
        float v = g_h1[((size_t)b * 128 + c) * N1 + n0 + nn];
        v = (v - g_volstat[b][g][0]) * g_volstat[b][g][1];
        v = v * g1[c] + be1[c];
        hn[c][nn] = (v >= 0.f) ? v : a1 * v;
    }
    __syncthreads();
    for (int i = t; i < FC * 32; i += 256) {
        int o = i >> 5, nn = i & 31;
        float acc = b2[o];
        const float* w = W2 + o * 128;
#pragma unroll 16
        for (int c = 0; c < 128; c++) acc += w[c] * hn[c][nn];
        out[((size_t)b * FC + o) * N1 + n0 + nn] = acc;
    }
}

// ---------------- K6: knn branch -> out += ----------------
// one warp per row; 8 rows / block; grid (N1/8, B)
__global__ void knnout_kernel(const float* __restrict__ coords, const float* __restrict__ coords2,
                              const float* __restrict__ Wk, const float* __restrict__ bk,
                              const float* __restrict__ gk, const float* __restrict__ bek,
                              const float* __restrict__ akp,
                              const float* __restrict__ Wo, const float* __restrict__ bo,
                              float* __restrict__ out) {
    int b = blockIdx.y;
    int warp = threadIdx.x >> 5;
    int lane = threadIdx.x & 31;
    int n = blockIdx.x * 8 + warp;
    __shared__ float smaxh[8][64];
    float ak = akp[0];

    float cx = coords[((size_t)b * N1 + n) * 3 + 0];
    float cy = coords[((size_t)b * N1 + n) * 3 + 1];
    float cz = coords[((size_t)b * N1 + n) * 3 + 2];
    const float* c2 = coords2 + (size_t)b * N2 * 3;

    int j = g_nbr[((size_t)b * N1 + n) * KK + lane];
    float e0 = g_corr[((size_t)b * N1 + n) * N2 + j];
    float e1 = c2[j * 3 + 0] - cx;
    float e2 = c2[j * 3 + 1] - cy;
    float e3 = c2[j * 3 + 2] - cz;

#pragma unroll 8
    for (int c = 0; c < 64; c++) {
        const float* w = Wk + c * 4;
        float h = bk[c] + w[0] * e0 + w[1] * e1 + w[2] * e2 + w[3] * e3;
        int g = c >> 3;
        h = (h - g_knnstat[b][g][0]) * g_knnstat[b][g][1];
        h = h * gk[c] + bek[c];
        h = (h >= 0.f) ? h : ak * h;
#pragma unroll
        for (int off = 16; off; off >>= 1) h = fmaxf(h, __shfl_xor_sync(0xffffffffu, h, off));
        if (lane == 0) smaxh[warp][c] = h;
    }
    __syncwarp();

#pragma unroll
    for (int o = lane; o < FC; o += 32) {
        float acc = bo[o];
        const float* w = Wo + o * 64;
#pragma unroll 16
        for (int c = 0; c < 64; c++) acc += w[c] * smaxh[warp][c];
        out[((size_t)b * FC + o) * N1 + n] += acc;
    }
}

// ---------------- launch ----------------
extern "C" void kernel_launch(void* const* d_in, const int* in_sizes, int n_in,
                              void* d_out, int out_size) {
    const float* coords  = (const float*)d_in[0];
    const float* coords2 = (const float*)d_in[1];
    const float* fmap1   = (const float*)d_in[2];
    const float* fmap2   = (const float*)d_in[3];
    const float* W1  = (const float*)d_in[4];
    const float* b1  = (const float*)d_in[5];
    const float* g1  = (const float*)d_in[6];
    const float* be1 = (const float*)d_in[7];
    const float* a1  = (const float*)d_in[8];
    const float* W2  = (const float*)d_in[9];
    const float* b2  = (const float*)d_in[10];
    const float* Wk  = (const float*)d_in[11];
    const float* bk  = (const float*)d_in[12];
    const float* gk  = (const float*)d_in[13];
    const float* bek = (const float*)d_in[14];
    const float* ak  = (const float*)d_in[15];
    const float* Wo  = (const float*)d_in[16];
    const float* bo  = (const float*)d_in[17];
    float* out = (float*)d_out;

    zero_stats_kernel<<<1, 256>>>();
    corr_kernel<<<dim3(N1 / 64, N2 / 64, BB), 256>>>(fmap1, fmap2);
    row_kernel<<<dim3(N1 / 8, BB), 256>>>(coords, coords2);
    h1_kernel<<<dim3(N1 / 128, BB), 128>>>(W1, b1);
    finalize_kernel<<<1, 64>>>(Wk, bk);
    volout_kernel<<<dim3(N1 / 32, BB), 256>>>(g1, be1, a1, W2, b2, out);
    knnout_kernel<<<dim3(N1 / 8, BB), 256>>>(coords, coords2, Wk, bk, gk, bek, ak, Wo, bo, out);
}

// round 2
// speedup vs baseline: 1.1434x; 1.1434x over previous
#include <cuda_runtime.h>
#include <cuda_bf16.h>
#include <math.h>

#define BB   8
#define N1   2048
#define N2   512
#define DD   128
#define KK   32
#define R3   27
#define NCH  81      // 3*27
#define FC   192

// ---------------- scratch (device globals; no allocs allowed) ----------------
__device__ float  g_corr[BB * N1 * N2];          // 32 MB
__device__ float  g_vol [BB * NCH * N1];         // 5.3 MB
__device__ float  g_h1  [BB * 128 * N1];         // 8.4 MB
__device__ int    g_nbr [BB * N1 * KK];          // 2 MB
__device__ double g_volsum[BB][8][2];            // sum, sumsq per (b, group)
__device__ double g_knnmom[BB][14];              // mu(4) + upper-tri E[ee^T](10)
__device__ float  g_volstat[BB][8][2];           // mean, rstd
__device__ float  g_knnstat[BB][8][2];           // mean, rstd

// ---------------- K0: zero the stat accumulators ----------------
__global__ void zero_stats_kernel() {
    int t = threadIdx.x;
    double* vs = &g_volsum[0][0][0];
    double* km = &g_knnmom[0][0];
    if (t < BB * 8 * 2) vs[t] = 0.0;
    if (t < BB * 14)    km[t] = 0.0;
}

// ---------------- K1: corr = fmap1^T @ fmap2 / sqrt(D) ----------------
// tile 128(n1) x 64(n2), 256 threads, 8x4 per thread
__global__ __launch_bounds__(256) void corr_kernel(const float* __restrict__ f1,
                                                   const float* __restrict__ f2) {
    int b  = blockIdx.z;
    int n0 = blockIdx.x * 128;
    int m0 = blockIdx.y * 64;
    __shared__ float As[16][128];
    __shared__ float Bs[16][64];
    int tx = threadIdx.x & 15;   // n2 dir
    int ty = threadIdx.x >> 4;   // n1 dir
    float acc[8][4];
#pragma unroll
    for (int i = 0; i < 8; i++)
#pragma unroll
        for (int j = 0; j < 4; j++) acc[i][j] = 0.f;

    const float* A = f1 + (size_t)b * DD * N1;
    const float* Bp = f2 + (size_t)b * DD * N2;
    for (int k0 = 0; k0 < DD; k0 += 16) {
#pragma unroll
        for (int i = threadIdx.x; i < 16 * 128; i += 256) {
            int d = i >> 7, c = i & 127;
            As[d][c] = A[(k0 + d) * N1 + n0 + c];
        }
#pragma unroll
        for (int i = threadIdx.x; i < 16 * 64; i += 256) {
            int d = i >> 6, c = i & 63;
            Bs[d][c] = Bp[(k0 + d) * N2 + m0 + c];
        }
        __syncthreads();
#pragma unroll
        for (int kk = 0; kk < 16; kk++) {
            float4 a0 = *(const float4*)&As[kk][ty * 8];
            float4 a1 = *(const float4*)&As[kk][ty * 8 + 4];
            float4 b0 = *(const float4*)&Bs[kk][tx * 4];
            float av[8] = {a0.x, a0.y, a0.z, a0.w, a1.x, a1.y, a1.z, a1.w};
            float bv[4] = {b0.x, b0.y, b0.z, b0.w};
#pragma unroll
            for (int i = 0; i < 8; i++)
#pragma unroll
                for (int j = 0; j < 4; j++) acc[i][j] += av[i] * bv[j];
        }
        __syncthreads();
    }
    const float s = 0.08838834764831845f;  // 1/sqrt(128)
#pragma unroll
    for (int i = 0; i < 8; i++) {
        int n = n0 + ty * 8 + i;
        float4 v;
        v.x = acc[i][0] * s; v.y = acc[i][1] * s; v.z = acc[i][2] * s; v.w = acc[i][3] * s;
        *(float4*)(g_corr + ((size_t)b * N1 + n) * N2 + m0 + tx * 4) = v;
    }
}

// ---------------- K2: per-row pass: voxel bins + KNN select + e-moments ----------------
// one warp per row n; 8 rows per block; grid (N1/8, B)
__global__ void row_kernel(const float* __restrict__ coords,
                           const float* __restrict__ coords2) {
    int b    = blockIdx.y;
    int warp = threadIdx.x >> 5;
    int lane = threadIdx.x & 31;
    int n    = blockIdx.x * 8 + warp;

    __shared__ float sadd[8][NCH];
    __shared__ float scnt[8][NCH];
    __shared__ int   sknn[8][KK];
    __shared__ float smom[14];

    if (threadIdx.x < 14) smom[threadIdx.x] = 0.f;
    for (int q = lane; q < NCH; q += 32) { sadd[warp][q] = 0.f; scnt[warp][q] = 0.f; }
    __syncthreads();

    float cx = coords[((size_t)b * N1 + n) * 3 + 0];
    float cy = coords[((size_t)b * N1 + n) * 3 + 1];
    float cz = coords[((size_t)b * N1 + n) * 3 + 2];
    const float* crow = g_corr + ((size_t)b * N1 + n) * N2;
    const float* c2 = coords2 + (size_t)b * N2 * 3;

    float dloc[16];
#pragma unroll 4
    for (int s = 0; s < 16; s++) {
        int m = lane + s * 32;
        float qx = c2[m * 3 + 0] - cx;
        float qy = c2[m * 3 + 1] - cy;
        float qz = c2[m * 3 + 2] - cz;
        dloc[s] = qx * qx + qy * qy + qz * qz;
        float mx = fmaxf(fabsf(qx), fmaxf(fabsf(qy), fabsf(qz)));
        if (mx < 1.5f) {
            float cv = crow[m];
#pragma unroll
            for (int lvl = 0; lvl < 3; lvl++) {
                float inv = (lvl == 0) ? 4.f : (lvl == 1 ? 2.f : 1.f);
                float vx = rintf(qx * inv), vy = rintf(qy * inv), vz = rintf(qz * inv);
                if (fabsf(vx) <= 1.f && fabsf(vy) <= 1.f && fabsf(vz) <= 1.f) {
                    int idx = lvl * 27 + ((int)vx + 1) * 9 + ((int)vy + 1) * 3 + ((int)vz + 1);
                    atomicAdd(&sadd[warp][idx], cv);
                    atomicAdd(&scnt[warp][idx], 1.f);
                }
            }
        }
    }
    __syncwarp();

    // top-32 smallest dist (index tiebreak = reference top_k semantics)
    for (int k = 0; k < KK; k++) {
        float bv = 3.4e38f; int bs = 16;
#pragma unroll
        for (int s = 0; s < 16; s++) {
            if (dloc[s] < bv) { bv = dloc[s]; bs = s; }
        }
        int bm = lane + bs * 32;
#pragma unroll
        for (int off = 16; off; off >>= 1) {
            float ov = __shfl_xor_sync(0xffffffffu, bv, off);
            int   om = __shfl_xor_sync(0xffffffffu, bm, off);
            if (ov < bv || (ov == bv && om < bm)) { bv = ov; bm = om; }
        }
        if (lane == (bm & 31)) {
            int ws = bm >> 5;
#pragma unroll
            for (int s = 0; s < 16; s++) if (s == ws) dloc[s] = 3.4e38f;
        }
        if (lane == 0) sknn[warp][k] = bm;
    }
    __syncwarp();

    int j = sknn[warp][lane];
    g_nbr[((size_t)b * N1 + n) * KK + lane] = j;
    float e0 = crow[j];
    float e1 = c2[j * 3 + 0] - cx;
    float e2 = c2[j * 3 + 1] - cy;
    float e3 = c2[j * 3 + 2] - cz;

    float mv[14] = { e0, e1, e2, e3,
                     e0*e0, e0*e1, e0*e2, e0*e3,
                     e1*e1, e1*e2, e1*e3,
                     e2*e2, e2*e3, e3*e3 };
#pragma unroll
    for (int i = 0; i < 14; i++) {
        float v = mv[i];
#pragma unroll
        for (int off = 16; off; off >>= 1) v += __shfl_xor_sync(0xffffffffu, v, off);
        if (lane == 0) atomicAdd(&smom[i], v);
    }

    // write voxel features (scatter mean)
    for (int q = lane; q < NCH; q += 32) {
        float cnt = scnt[warp][q];
        g_vol[((size_t)b * NCH + q) * N1 + n] = sadd[warp][q] / fmaxf(cnt, 1.f);
    }
    __syncthreads();
    if (threadIdx.x < 14) atomicAdd(&g_knnmom[b][threadIdx.x], (double)smom[threadIdx.x]);
}

// ---------------- K3: h1 = W1 @ vol + b1, plus GN partial stats ----------------
// GEMM: M=128 ch, K=81, N=2048/batch. tile 128x64, 8x4/thread, K-chunks of 27.
__global__ __launch_bounds__(256) void h1_kernel(const float* __restrict__ W1,
                                                 const float* __restrict__ b1) {
    int b  = blockIdx.y;
    int n0 = blockIdx.x * 64;
    int tx = threadIdx.x & 15;   // point dir (4 per thread)
    int ty = threadIdx.x >> 4;   // channel dir (8 per thread)
    __shared__ float Ws[27][128];
    __shared__ float Vs[27][64];
    __shared__ float sgs[8], sgss[8];
    if (threadIdx.x < 8) { sgs[threadIdx.x] = 0.f; sgss[threadIdx.x] = 0.f; }

    float acc[8][4];
#pragma unroll
    for (int i = 0; i < 8; i++)
#pragma unroll
        for (int j = 0; j < 4; j++) acc[i][j] = 0.f;

    for (int chunk = 0; chunk < 3; chunk++) {
        int q0 = chunk * 27;
        for (int i = threadIdx.x; i < 27 * 128; i += 256) {
            int q = i >> 7, c = i & 127;
            Ws[q][c] = W1[c * NCH + q0 + q];
        }
        for (int i = threadIdx.x; i < 27 * 64; i += 256) {
            int q = i >> 6, c = i & 63;
            Vs[q][c] = g_vol[((size_t)b * NCH + q0 + q) * N1 + n0 + c];
        }
        __syncthreads();
#pragma unroll
        for (int q = 0; q < 27; q++) {
            float4 a0 = *(const float4*)&Ws[q][ty * 8];
            float4 a1 = *(const float4*)&Ws[q][ty * 8 + 4];
            float4 b0 = *(const float4*)&Vs[q][tx * 4];
            float av[8] = {a0.x, a0.y, a0.z, a0.w, a1.x, a1.y, a1.z, a1.w};
            float bv[4] = {b0.x, b0.y, b0.z, b0.w};
#pragma unroll
            for (int i = 0; i < 8; i++)
#pragma unroll
                for (int j = 0; j < 4; j++) acc[i][j] += av[i] * bv[j];
        }
        __syncthreads();
    }

    // epilogue: +bias, write, GN partial stats. All 8 channels of a thread are
    // in one group (8-aligned run within 16-wide groups): g = ty>>1.
    float ls = 0.f, lss = 0.f;
#pragma unroll
    for (int i = 0; i < 8; i++) {
        int c = ty * 8 + i;
        float bias = b1[c];
        float4 v;
        v.x = acc[i][0] + bias; v.y = acc[i][1] + bias;
        v.z = acc[i][2] + bias; v.w = acc[i][3] + bias;
        *(float4*)(g_h1 + ((size_t)b * 128 + c) * N1 + n0 + tx * 4) = v;
        ls  += v.x + v.y + v.z + v.w;
        lss += v.x * v.x + v.y * v.y + v.z * v.z + v.w * v.w;
    }
    int g = ty >> 1;
    atomicAdd(&sgs[g], ls);
    atomicAdd(&sgss[g], lss);
    __syncthreads();
    if (threadIdx.x < 8) {
        atomicAdd(&g_volsum[b][threadIdx.x][0], (double)sgs[threadIdx.x]);
        atomicAdd(&g_volsum[b][threadIdx.x][1], (double)sgss[threadIdx.x]);
    }
}

// ---------------- K4: finalize stats (vol GN + analytic knn GN) ----------------
__global__ void finalize_kernel(const float* __restrict__ Wk, const float* __restrict__ bk) {
    int t = threadIdx.x;
    if (t >= 64) return;
    int b = t >> 3, g = t & 7;

    // vol branch
    {
        double cnt = 16.0 * (double)N1;
        double mean = g_volsum[b][g][0] / cnt;
        double var = g_volsum[b][g][1] / cnt - mean * mean;
        g_volstat[b][g][0] = (float)mean;
        g_volstat[b][g][1] = (float)(1.0 / sqrt(var + 1e-5));
    }
    // knn branch (h = Wk e + bk is linear in e)
    {
        double cnt = (double)N1 * (double)KK;
        double mu[4];
#pragma unroll
        for (int i = 0; i < 4; i++) mu[i] = g_knnmom[b][i] / cnt;
        double S[4][4];
        const int pi[10][2] = {{0,0},{0,1},{0,2},{0,3},{1,1},{1,2},{1,3},{2,2},{2,3},{3,3}};
#pragma unroll
        for (int p = 0; p < 10; p++) {
            double v = g_knnmom[b][4 + p] / cnt;
            S[pi[p][0]][pi[p][1]] = v;
            S[pi[p][1]][pi[p][0]] = v;
        }
        double sm = 0.0, s2 = 0.0;
        for (int c = g * 8; c < g * 8 + 8; c++) {
            double w[4] = { (double)Wk[c*4+0], (double)Wk[c*4+1], (double)Wk[c*4+2], (double)Wk[c*4+3] };
            double bb = (double)bk[c];
            double wm = w[0]*mu[0] + w[1]*mu[1] + w[2]*mu[2] + w[3]*mu[3];
            double q = 0.0;
#pragma unroll
            for (int i = 0; i < 4; i++)
#pragma unroll
                for (int jj = 0; jj < 4; jj++) q += w[i] * S[i][jj] * w[jj];
            double m1 = wm + bb;
            double m2 = q + 2.0 * bb * wm + bb * bb;
            sm += m1; s2 += m2;
        }
        sm *= 0.125; s2 *= 0.125;
        double var = s2 - sm * sm;
        g_knnstat[b][g][0] = (float)sm;
        g_knnstat[b][g][1] = (float)(1.0 / sqrt(var + 1e-5));
    }
}

// ---------------- K5: vol_out = W2 @ prelu(GN(h1)) + b2 -> out ----------------
// GEMM: M=192 (FC), K=128, N=2048/batch. tile 64(o) x 128(n), 4x8/thread.
__global__ __launch_bounds__(256) void volout_kernel(const float* __restrict__ g1, const float* __restrict__ be1,
                              const float* __restrict__ a1p,
                              const float* __restrict__ W2, const float* __restrict__ b2,
                              float* __restrict__ out) {
    int b  = blockIdx.z;
    int o0 = blockIdx.y * 64;
    int n0 = blockIdx.x * 128;
    int tx = threadIdx.x & 15;   // n dir (8 per thread)
    int ty = threadIdx.x >> 4;   // o dir (4 per thread)
    __shared__ float Ws[16][64];
    __shared__ float Hs[16][128];
    float a1 = a1p[0];

    float acc[4][8];
#pragma unroll
    for (int i = 0; i < 4; i++)
#pragma unroll
        for (int j = 0; j < 8; j++) acc[i][j] = 0.f;

    for (int k0 = 0; k0 < 128; k0 += 16) {
        for (int i = threadIdx.x; i < 16 * 64; i += 256) {
            int d = i >> 6, o = i & 63;
            Ws[d][o] = W2[(o0 + o) * 128 + k0 + d];
        }
        for (int i = threadIdx.x; i < 16 * 128; i += 256) {
            int d = i >> 7, c = i & 127;
            int k = k0 + d;
            float v = g_h1[((size_t)b * 128 + k) * N1 + n0 + c];
            int g = k >> 4;
            v = (v - g_volstat[b][g][0]) * g_volstat[b][g][1];
            v = v * g1[k] + be1[k];
            Hs[d][c] = (v >= 0.f) ? v : a1 * v;
        }
        __syncthreads();
#pragma unroll
        for (int kk = 0; kk < 16; kk++) {
            float4 a0 = *(const float4*)&Ws[kk][ty * 4];
            float4 b0 = *(const float4*)&Hs[kk][tx * 8];
            float4 b1v = *(const float4*)&Hs[kk][tx * 8 + 4];
            float av[4] = {a0.x, a0.y, a0.z, a0.w};
            float bv[8] = {b0.x, b0.y, b0.z, b0.w, b1v.x, b1v.y, b1v.z, b1v.w};
#pragma unroll
            for (int i = 0; i < 4; i++)
#pragma unroll
                for (int j = 0; j < 8; j++) acc[i][j] += av[i] * bv[j];
        }
        __syncthreads();
    }
#pragma unroll
    for (int i = 0; i < 4; i++) {
        int o = o0 + ty * 4 + i;
        float bias = b2[o];
        float* dst = out + ((size_t)b * FC + o) * N1 + n0 + tx * 8;
        float4 v0, v1;
        v0.x = acc[i][0] + bias; v0.y = acc[i][1] + bias;
        v0.z = acc[i][2] + bias; v0.w = acc[i][3] + bias;
        v1.x = acc[i][4] + bias; v1.y = acc[i][5] + bias;
        v1.z = acc[i][6] + bias; v1.w = acc[i][7] + bias;
        *(float4*)dst = v0;
        *(float4*)(dst + 4) = v1;
    }
}

// ---------------- K6: knn branch -> out += ----------------
// one warp per row; 8 rows / block; grid (N1/8, B)
__global__ void knnout_kernel(const float* __restrict__ coords, const float* __restrict__ coords2,
                              const float* __restrict__ Wk, const float* __restrict__ bk,
                              const float* __restrict__ gk, const float* __restrict__ bek,
                              const float* __restrict__ akp,
                              const float* __restrict__ Wo, const float* __restrict__ bo,
                              float* __restrict__ out) {
    int b = blockIdx.y;
    int warp = threadIdx.x >> 5;
    int lane = threadIdx.x & 31;
    int n = blockIdx.x * 8 + warp;
    __shared__ float smaxh[8][64];
    float ak = akp[0];

    float cx = coords[((size_t)b * N1 + n) * 3 + 0];
    float cy = coords[((size_t)b * N1 + n) * 3 + 1];
    float cz = coords[((size_t)b * N1 + n) * 3 + 2];
    const float* c2 = coords2 + (size_t)b * N2 * 3;

    int j = g_nbr[((size_t)b * N1 + n) * KK + lane];
    float e0 = g_corr[((size_t)b * N1 + n) * N2 + j];
    float e1 = c2[j * 3 + 0] - cx;
    float e2 = c2[j * 3 + 1] - cy;
    float e3 = c2[j * 3 + 2] - cz;

#pragma unroll 8
    for (int c = 0; c < 64; c++) {
        const float* w = Wk + c * 4;
        float h = bk[c] + w[0] * e0 + w[1] * e1 + w[2] * e2 + w[3] * e3;
        int g = c >> 3;
        h = (h - g_knnstat[b][g][0]) * g_knnstat[b][g][1];
        h = h * gk[c] + bek[c];
        h = (h >= 0.f) ? h : ak * h;
#pragma unroll
        for (int off = 16; off; off >>= 1) h = fmaxf(h, __shfl_xor_sync(0xffffffffu, h, off));
        if (lane == 0) smaxh[warp][c] = h;
    }
    __syncwarp();

#pragma unroll
    for (int o = lane; o < FC; o += 32) {
        float acc = bo[o];
        const float* w = Wo + o * 64;
#pragma unroll 16
        for (int c = 0; c < 64; c++) acc += w[c] * smaxh[warp][c];
        out[((size_t)b * FC + o) * N1 + n] += acc;
    }
}

// ---------------- launch ----------------
extern "C" void kernel_launch(void* const* d_in, const int* in_sizes, int n_in,
                              void* d_out, int out_size) {
    const float* coords  = (const float*)d_in[0];
    const float* coords2 = (const float*)d_in[1];
    const float* fmap1   = (const float*)d_in[2];
    const float* fmap2   = (const float*)d_in[3];
    const float* W1  = (const float*)d_in[4];
    const float* b1  = (const float*)d_in[5];
    const float* g1  = (const float*)d_in[6];
    const float* be1 = (const float*)d_in[7];
    const float* a1  = (const float*)d_in[8];
    const float* W2  = (const float*)d_in[9];
    const float* b2  = (const float*)d_in[10];
    const float* Wk  = (const float*)d_in[11];
    const float* bk  = (const float*)d_in[12];
    const float* gk  = (const float*)d_in[13];
    const float* bek = (const float*)d_in[14];
    const float* ak  = (const float*)d_in[15];
    const float* Wo  = (const float*)d_in[16];
    const float* bo  = (const float*)d_in[17];
    float* out = (float*)d_out;

    zero_stats_kernel<<<1, 256>>>();
    corr_kernel<<<dim3(N1 / 128, N2 / 64, BB), 256>>>(fmap1, fmap2);
    row_kernel<<<dim3(N1 / 8, BB), 256>>>(coords, coords2);
    h1_kernel<<<dim3(N1 / 64, BB), 256>>>(W1, b1);
    finalize_kernel<<<1, 64>>>(Wk, bk);
    volout_kernel<<<dim3(N1 / 128, FC / 64, BB), 256>>>(g1, be1, a1, W2, b2, out);
    knnout_kernel<<<dim3(N1 / 8, BB), 256>>>(coords, coords2, Wk, bk, gk, bek, ak, Wo, bo, out);
}

// round 3
// speedup vs baseline: 2.5771x; 2.2538x over previous
#include <cuda_runtime.h>
#include <cuda_bf16.h>
#include <math.h>

#define BB   8
#define N1   2048
#define N2   512
#define DD   128
#define KK   32
#define R3   27
#define NCH  81      // 3*27
#define FC   192

// ---------------- scratch (device globals; no allocs allowed) ----------------
__device__ float  g_corr[BB * N1 * N2];          // 32 MB
__device__ float  g_vol [BB * N1 * NCH];         // [b][n][81]
__device__ float  g_h1  [BB * 128 * N1];         // [b][c][n]
__device__ float  g_hmm [BB * N1 * 128];         // [b][n][c: 0..63 max, 64..127 min]
__device__ float  g_W1T [NCH * 128];             // [q][c]
__device__ double g_volsum[BB][8][2];            // sum, sumsq per (b, group)
__device__ double g_knnmom[BB][14];              // mu(4) + upper-tri E[ee^T](10)
__device__ float  g_volstat[BB][8][2];           // mean, rstd
__device__ float  g_knnstat[BB][8][2];           // mean, rstd

// order-preserving float<->uint maps (no NaNs in this data)
__device__ __forceinline__ unsigned f2u(float f) {
    unsigned u = __float_as_uint(f);
    return (u & 0x80000000u) ? ~u : (u | 0x80000000u);
}
__device__ __forceinline__ float u2f(unsigned u) {
    return (u & 0x80000000u) ? __uint_as_float(u ^ 0x80000000u) : __uint_as_float(~u);
}

// ---------------- K0: zero the stat accumulators ----------------
__global__ void zero_stats_kernel() {
    int t = threadIdx.x;
    double* vs = &g_volsum[0][0][0];
    double* km = &g_knnmom[0][0];
    if (t < BB * 8 * 2) vs[t] = 0.0;
    if (t < BB * 14)    km[t] = 0.0;
}

// ---------------- K1: corr = fmap1^T @ fmap2 / sqrt(D) ----------------
// tile 128(n1) x 64(n2), 256 threads, 8x4 per thread
__global__ __launch_bounds__(256) void corr_kernel(const float* __restrict__ f1,
                                                   const float* __restrict__ f2) {
    int b  = blockIdx.z;
    int n0 = blockIdx.x * 128;
    int m0 = blockIdx.y * 64;
    __shared__ float As[16][128];
    __shared__ float Bs[16][64];
    int tx = threadIdx.x & 15;   // n2 dir
    int ty = threadIdx.x >> 4;   // n1 dir
    float acc[8][4];
#pragma unroll
    for (int i = 0; i < 8; i++)
#pragma unroll
        for (int j = 0; j < 4; j++) acc[i][j] = 0.f;

    const float* A = f1 + (size_t)b * DD * N1;
    const float* Bp = f2 + (size_t)b * DD * N2;
    for (int k0 = 0; k0 < DD; k0 += 16) {
#pragma unroll
        for (int i = threadIdx.x; i < 16 * 128; i += 256) {
            int d = i >> 7, c = i & 127;
            As[d][c] = A[(k0 + d) * N1 + n0 + c];
        }
#pragma unroll
        for (int i = threadIdx.x; i < 16 * 64; i += 256) {
            int d = i >> 6, c = i & 63;
            Bs[d][c] = Bp[(k0 + d) * N2 + m0 + c];
        }
        __syncthreads();
#pragma unroll
        for (int kk = 0; kk < 16; kk++) {
            float4 a0 = *(const float4*)&As[kk][ty * 8];
            float4 a1 = *(const float4*)&As[kk][ty * 8 + 4];
            float4 b0 = *(const float4*)&Bs[kk][tx * 4];
            float av[8] = {a0.x, a0.y, a0.z, a0.w, a1.x, a1.y, a1.z, a1.w};
            float bv[4] = {b0.x, b0.y, b0.z, b0.w};
#pragma unroll
            for (int i = 0; i < 8; i++)
#pragma unroll
                for (int j = 0; j < 4; j++) acc[i][j] += av[i] * bv[j];
        }
        __syncthreads();
    }
    const float s = 0.08838834764831845f;  // 1/sqrt(128)
#pragma unroll
    for (int i = 0; i < 8; i++) {
        int n = n0 + ty * 8 + i;
        float4 v;
        v.x = acc[i][0] * s; v.y = acc[i][1] * s; v.z = acc[i][2] * s; v.w = acc[i][3] * s;
        *(float4*)(g_corr + ((size_t)b * N1 + n) * N2 + m0 + tx * 4) = v;
    }
}

// ---------------- K1.5: transpose W1 -> [q][c] (also fills profile slot 2) ----
__global__ void w1t_kernel(const float* __restrict__ W1) {
    int i = blockIdx.x * 256 + threadIdx.x;
    if (i < NCH * 128) {
        int q = i >> 7, c = i & 127;
        g_W1T[q * 128 + c] = W1[c * NCH + q];
    }
}

// ---------------- K2: per-row pass: voxel bins + KNN + e-moments + h minmax ---
// one warp per row n; 8 rows per block; grid (N1/8, B)
__global__ void row_kernel(const float* __restrict__ coords,
                           const float* __restrict__ coords2,
                           const float* __restrict__ Wk,
                           const float* __restrict__ bk) {
    int b    = blockIdx.y;
    int warp = threadIdx.x >> 5;
    int lane = threadIdx.x & 31;
    int n    = blockIdx.x * 8 + warp;

    __shared__ float sadd[8][NCH];
    __shared__ float scnt[8][NCH];
    __shared__ int   sknn[8][KK];
    __shared__ float smom[14];
    __shared__ float smm[8][128];

    if (threadIdx.x < 14) smom[threadIdx.x] = 0.f;
    for (int q = lane; q < NCH; q += 32) { sadd[warp][q] = 0.f; scnt[warp][q] = 0.f; }
    __syncthreads();

    float cx = coords[((size_t)b * N1 + n) * 3 + 0];
    float cy = coords[((size_t)b * N1 + n) * 3 + 1];
    float cz = coords[((size_t)b * N1 + n) * 3 + 2];
    const float* crow = g_corr + ((size_t)b * N1 + n) * N2;
    const float* c2 = coords2 + (size_t)b * N2 * 3;

    float dloc[16];
#pragma unroll 4
    for (int s = 0; s < 16; s++) {
        int m = lane + s * 32;
        float qx = c2[m * 3 + 0] - cx;
        float qy = c2[m * 3 + 1] - cy;
        float qz = c2[m * 3 + 2] - cz;
        dloc[s] = qx * qx + qy * qy + qz * qz;
        float mx = fmaxf(fabsf(qx), fmaxf(fabsf(qy), fabsf(qz)));
        if (mx < 1.5f) {
            float cv = crow[m];
#pragma unroll
            for (int lvl = 0; lvl < 3; lvl++) {
                float inv = (lvl == 0) ? 4.f : (lvl == 1 ? 2.f : 1.f);
                float vx = rintf(qx * inv), vy = rintf(qy * inv), vz = rintf(qz * inv);
                if (fabsf(vx) <= 1.f && fabsf(vy) <= 1.f && fabsf(vz) <= 1.f) {
                    int idx = lvl * 27 + ((int)vx + 1) * 9 + ((int)vy + 1) * 3 + ((int)vz + 1);
                    atomicAdd(&sadd[warp][idx], cv);
                    atomicAdd(&scnt[warp][idx], 1.f);
                }
            }
        }
    }
    __syncwarp();

    // top-32 smallest dist (index tiebreak = reference top_k semantics)
    for (int k = 0; k < KK; k++) {
        float bv = 3.4e38f; int bs = 16;
#pragma unroll
        for (int s = 0; s < 16; s++) {
            if (dloc[s] < bv) { bv = dloc[s]; bs = s; }
        }
        int bm = lane + bs * 32;
#pragma unroll
        for (int off = 16; off; off >>= 1) {
            float ov = __shfl_xor_sync(0xffffffffu, bv, off);
            int   om = __shfl_xor_sync(0xffffffffu, bm, off);
            if (ov < bv || (ov == bv && om < bm)) { bv = ov; bm = om; }
        }
        if (lane == (bm & 31)) {
            int ws = bm >> 5;
#pragma unroll
            for (int s = 0; s < 16; s++) if (s == ws) dloc[s] = 3.4e38f;
        }
        if (lane == 0) sknn[warp][k] = bm;
    }
    __syncwarp();

    int j = sknn[warp][lane];
    float e0 = crow[j];
    float e1 = c2[j * 3 + 0] - cx;
    float e2 = c2[j * 3 + 1] - cy;
    float e3 = c2[j * 3 + 2] - cz;

    float mv[14] = { e0, e1, e2, e3,
                     e0*e0, e0*e1, e0*e2, e0*e3,
                     e1*e1, e1*e2, e1*e3,
                     e2*e2, e2*e3, e3*e3 };
#pragma unroll
    for (int i = 0; i < 14; i++) {
        float v = mv[i];
#pragma unroll
        for (int off = 16; off; off >>= 1) v += __shfl_xor_sync(0xffffffffu, v, off);
        if (lane == 0) atomicAdd(&smom[i], v);
    }

    // per-channel max/min of raw h = Wk.e + bk over the 32 selected neighbors
#pragma unroll 8
    for (int c = 0; c < 64; c++) {
        float4 w = *(const float4*)(Wk + c * 4);
        float h = bk[c] + w.x * e0 + w.y * e1 + w.z * e2 + w.w * e3;
        unsigned u = f2u(h);
        unsigned umax = __reduce_max_sync(0xffffffffu, u);
        unsigned umin = __reduce_min_sync(0xffffffffu, u);
        if (lane == (c & 31)) {
            smm[warp][c]      = u2f(umax);
            smm[warp][64 + c] = u2f(umin);
        }
    }

    // voxel features (scatter mean), coalesced row layout [n][81]
    for (int q = lane; q < NCH; q += 32) {
        float cnt = scnt[warp][q];
        g_vol[((size_t)b * N1 + n) * NCH + q] = sadd[warp][q] / fmaxf(cnt, 1.f);
    }
    __syncthreads();
    if (threadIdx.x < 14) atomicAdd(&g_knnmom[b][threadIdx.x], (double)smom[threadIdx.x]);
    // coalesced hmm write
    int nb = blockIdx.x * 8;
    for (int i = threadIdx.x; i < 8 * 128; i += 256) {
        int r = i >> 7;
        g_hmm[((size_t)b * N1 + nb + r) * 128 + (i & 127)] = smm[r][i & 127];
    }
}

// ---------------- K3: h1 = W1 @ vol + b1, plus GN partial stats ----------------
// GEMM: M=128 ch, K=81, N=2048/batch. tile 128x64, 8x4/thread, K-chunks of 27.
__global__ __launch_bounds__(256) void h1_kernel(const float* __restrict__ b1) {
    int b  = blockIdx.y;
    int n0 = blockIdx.x * 64;
    int tx = threadIdx.x & 15;   // point dir (4 per thread)
    int ty = threadIdx.x >> 4;   // channel dir (8 per thread)
    __shared__ float Ws[27][128];
    __shared__ float Vs[27][64];
    __shared__ float sgs[8], sgss[8];
    if (threadIdx.x < 8) { sgs[threadIdx.x] = 0.f; sgss[threadIdx.x] = 0.f; }

    float acc[8][4];
#pragma unroll
    for (int i = 0; i < 8; i++)
#pragma unroll
        for (int j = 0; j < 4; j++) acc[i][j] = 0.f;

    for (int chunk = 0; chunk < 3; chunk++) {
        int q0 = chunk * 27;
        for (int i = threadIdx.x; i < 27 * 128; i += 256) {
            int q = i >> 7, c = i & 127;
            Ws[q][c] = g_W1T[(q0 + q) * 128 + c];
        }
        for (int i = threadIdx.x; i < 27 * 64; i += 256) {
            int nn = i / 27, q = i - nn * 27;
            Vs[q][nn] = g_vol[((size_t)b * N1 + n0 + nn) * NCH + q0 + q];
        }
        __syncthreads();
#pragma unroll
        for (int q = 0; q < 27; q++) {
            float4 a0 = *(const float4*)&Ws[q][ty * 8];
            float4 a1 = *(const float4*)&Ws[q][ty * 8 + 4];
            float4 b0 = *(const float4*)&Vs[q][tx * 4];
            float av[8] = {a0.x, a0.y, a0.z, a0.w, a1.x, a1.y, a1.z, a1.w};
            float bv[4] = {b0.x, b0.y, b0.z, b0.w};
#pragma unroll
            for (int i = 0; i < 8; i++)
#pragma unroll
                for (int j = 0; j < 4; j++) acc[i][j] += av[i] * bv[j];
        }
        __syncthreads();
    }

    float ls = 0.f, lss = 0.f;
#pragma unroll
    for (int i = 0; i < 8; i++) {
        int c = ty * 8 + i;
        float bias = b1[c];
        float4 v;
        v.x = acc[i][0] + bias; v.y = acc[i][1] + bias;
        v.z = acc[i][2] + bias; v.w = acc[i][3] + bias;
        *(float4*)(g_h1 + ((size_t)b * 128 + c) * N1 + n0 + tx * 4) = v;
        ls  += v.x + v.y + v.z + v.w;
        lss += v.x * v.x + v.y * v.y + v.z * v.z + v.w * v.w;
    }
    int g = ty >> 1;
    atomicAdd(&sgs[g], ls);
    atomicAdd(&sgss[g], lss);
    __syncthreads();
    if (threadIdx.x < 8) {
        atomicAdd(&g_volsum[b][threadIdx.x][0], (double)sgs[threadIdx.x]);
        atomicAdd(&g_volsum[b][threadIdx.x][1], (double)sgss[threadIdx.x]);
    }
}

// ---------------- K4: finalize stats (vol GN + analytic knn GN) ----------------
__global__ void finalize_kernel(const float* __restrict__ Wk, const float* __restrict__ bk) {
    int t = threadIdx.x;
    if (t >= 64) return;
    int b = t >> 3, g = t & 7;

    {
        double cnt = 16.0 * (double)N1;
        double mean = g_volsum[b][g][0] / cnt;
        double var = g_volsum[b][g][1] / cnt - mean * mean;
        g_volstat[b][g][0] = (float)mean;
        g_volstat[b][g][1] = (float)(1.0 / sqrt(var + 1e-5));
    }
    {
        double cnt = (double)N1 * (double)KK;
        double mu[4];
#pragma unroll
        for (int i = 0; i < 4; i++) mu[i] = g_knnmom[b][i] / cnt;
        double S[4][4];
        const int pi[10][2] = {{0,0},{0,1},{0,2},{0,3},{1,1},{1,2},{1,3},{2,2},{2,3},{3,3}};
#pragma unroll
        for (int p = 0; p < 10; p++) {
            double v = g_knnmom[b][4 + p] / cnt;
            S[pi[p][0]][pi[p][1]] = v;
            S[pi[p][1]][pi[p][0]] = v;
        }
        double sm = 0.0, s2 = 0.0;
        for (int c = g * 8; c < g * 8 + 8; c++) {
            double w[4] = { (double)Wk[c*4+0], (double)Wk[c*4+1], (double)Wk[c*4+2], (double)Wk[c*4+3] };
            double bb = (double)bk[c];
            double wm = w[0]*mu[0] + w[1]*mu[1] + w[2]*mu[2] + w[3]*mu[3];
            double q = 0.0;
#pragma unroll
            for (int i = 0; i < 4; i++)
#pragma unroll
                for (int jj = 0; jj < 4; jj++) q += w[i] * S[i][jj] * w[jj];
            double m1 = wm + bb;
            double m2 = q + 2.0 * bb * wm + bb * bb;
            sm += m1; s2 += m2;
        }
        sm *= 0.125; s2 *= 0.125;
        double var = s2 - sm * sm;
        g_knnstat[b][g][0] = (float)sm;
        g_knnstat[b][g][1] = (float)(1.0 / sqrt(var + 1e-5));
    }
}

// ---------------- K5: out = W2@prelu(GN(h1)) + Wo@prelu(GN(hpool)) + biases ----
// GEMM: M=192 (FC), K=192 (128 vol + 64 knn), N=2048/batch.
// tile 64(o) x 128(n), 4x8/thread.
__global__ __launch_bounds__(256) void out_kernel(const float* __restrict__ g1, const float* __restrict__ be1,
                              const float* __restrict__ a1p,
                              const float* __restrict__ W2, const float* __restrict__ b2,
                              const float* __restrict__ gk, const float* __restrict__ bek,
                              const float* __restrict__ akp,
                              const float* __restrict__ Wo, const float* __restrict__ bo,
                              float* __restrict__ out) {
    int b  = blockIdx.z;
    int o0 = blockIdx.y * 64;
    int n0 = blockIdx.x * 128;
    int tx = threadIdx.x & 15;   // n dir (8 per thread)
    int ty = threadIdx.x >> 4;   // o dir (4 per thread)
    __shared__ float Ws[16][64];
    __shared__ float Hs[16][128];
    float a1 = a1p[0], ak = akp[0];

    float acc[4][8];
#pragma unroll
    for (int i = 0; i < 4; i++)
#pragma unroll
        for (int j = 0; j < 8; j++) acc[i][j] = 0.f;

    for (int k0 = 0; k0 < 192; k0 += 16) {
        for (int i = threadIdx.x; i < 16 * 64; i += 256) {
            int d = i >> 6, o = i & 63;
            Ws[d][o] = (k0 < 128) ? W2[(o0 + o) * 128 + k0 + d]
                                  : Wo[(o0 + o) * 64 + (k0 - 128) + d];
        }
        if (k0 < 128) {
            for (int i = threadIdx.x; i < 16 * 128; i += 256) {
                int d = i >> 7, c = i & 127;
                int k = k0 + d;
                float v = g_h1[((size_t)b * 128 + k) * N1 + n0 + c];
                int g = k >> 4;
                v = (v - g_volstat[b][g][0]) * g_volstat[b][g][1];
                v = v * g1[k] + be1[k];
                Hs[d][c] = (v >= 0.f) ? v : a1 * v;
            }
        } else {
            int c0 = k0 - 128;
            for (int i = threadIdx.x; i < 16 * 128; i += 256) {
                int d = i & 15, nn = i >> 4;
                int c = c0 + d;
                int g = c >> 3;
                float slope = g_knnstat[b][g][1] * gk[c];
                const float* hm = g_hmm + ((size_t)b * N1 + n0 + nn) * 128;
                float hsel = (slope >= 0.f) ? hm[c] : hm[64 + c];
                float v = (hsel - g_knnstat[b][g][0]) * slope + bek[c];
                Hs[d][nn] = (v >= 0.f) ? v : ak * v;
            }
        }
        __syncthreads();
#pragma unroll
        for (int kk = 0; kk < 16; kk++) {
            float4 a0 = *(const float4*)&Ws[kk][ty * 4];
            float4 b0 = *(const float4*)&Hs[kk][tx * 8];
            float4 b1v = *(const float4*)&Hs[kk][tx * 8 + 4];
            float av[4] = {a0.x, a0.y, a0.z, a0.w};
            float bv[8] = {b0.x, b0.y, b0.z, b0.w, b1v.x, b1v.y, b1v.z, b1v.w};
#pragma unroll
            for (int i = 0; i < 4; i++)
#pragma unroll
                for (int j = 0; j < 8; j++) acc[i][j] += av[i] * bv[j];
        }
        __syncthreads();
    }
#pragma unroll
    for (int i = 0; i < 4; i++) {
        int o = o0 + ty * 4 + i;
        float bias = b2[o] + bo[o];
        float* dst = out + ((size_t)b * FC + o) * N1 + n0 + tx * 8;
        float4 v0, v1;
        v0.x = acc[i][0] + bias; v0.y = acc[i][1] + bias;
        v0.z = acc[i][2] + bias; v0.w = acc[i][3] + bias;
        v1.x = acc[i][4] + bias; v1.y = acc[i][5] + bias;
        v1.z = acc[i][6] + bias; v1.w = acc[i][7] + bias;
        *(float4*)dst = v0;
        *(float4*)(dst + 4) = v1;
    }
}

// ---------------- launch ----------------
extern "C" void kernel_launch(void* const* d_in, const int* in_sizes, int n_in,
                              void* d_out, int out_size) {
    const float* coords  = (const float*)d_in[0];
    const float* coords2 = (const float*)d_in[1];
    const float* fmap1   = (const float*)d_in[2];
    const float* fmap2   = (const float*)d_in[3];
    const float* W1  = (const float*)d_in[4];
    const float* b1  = (const float*)d_in[5];
    const float* g1  = (const float*)d_in[6];
    const float* be1 = (const float*)d_in[7];
    const float* a1  = (const float*)d_in[8];
    const float* W2  = (const float*)d_in[9];
    const float* b2  = (const float*)d_in[10];
    const float* Wk  = (const float*)d_in[11];
    const float* bk  = (const float*)d_in[12];
    const float* gk  = (const float*)d_in[13];
    const float* bek = (const float*)d_in[14];
    const float* ak  = (const float*)d_in[15];
    const float* Wo  = (const float*)d_in[16];
    const float* bo  = (const float*)d_in[17];
    float* out = (float*)d_out;

    zero_stats_kernel<<<1, 256>>>();                                   // 0
    corr_kernel<<<dim3(N1 / 128, N2 / 64, BB), 256>>>(fmap1, fmap2);   // 1
    w1t_kernel<<<(NCH * 128 + 255) / 256, 256>>>(W1);                  // 2
    row_kernel<<<dim3(N1 / 8, BB), 256>>>(coords, coords2, Wk, bk);    // 3 (profiled slot)
    h1_kernel<<<dim3(N1 / 64, BB), 256>>>(b1);                         // 4
    finalize_kernel<<<1, 64>>>(Wk, bk);                                // 5
    out_kernel<<<dim3(N1 / 128, FC / 64, BB), 256>>>(g1, be1, a1, W2, b2,
                                                     gk, bek, ak, Wo, bo, out); // 6
}